// round 12
// baseline (speedup 1.0000x reference)
#include <cuda_runtime.h>
#include <cuda_bf16.h>
#include <cstdint>

#define BATCH 256
#define TOBS  80
#define TTOT  160
#define HID   2048
#define HID4  8192
#define BH    (BATCH * HID)

#define NT      128                  // 4 warps: warp_m (2) x warp_n (2), warp tile 32x32
#define BM      64
#define BN      64
#define BK      64                   // K int8 per chunk = 64 bytes/row
#define NCH     32                   // 2048/64 chunks
#define NSTAGE  4
#define OFF_A1  0
#define OFF_A2  4096
#define OFF_B1  8192
#define OFF_B2  12288
#define STAGE_B 16384                // 4x4 KB
#define CTRL_B  1536
#define SMEM_DYN (1024 + CTRL_B + NSTAGE * STAGE_B)

#define QSCALE  16256.0f             // fixed-point scale (127*128)

// ---------------- persistent device state ----------------
__device__ float   g_c[BH];
__device__ int8_t  g_h1[2 * BH];     // h limb1, ping-pong
__device__ int8_t  g_h2[2 * BH];     // h limb2
__device__ int8_t  g_w1[(size_t)HID4 * HID];   // gate-interleaved W_hh limb1
__device__ int8_t  g_w2[(size_t)HID4 * HID];   // limb2
__device__ float   g_ws[HID4];       // per gate-row combined scale = amax/QSCALE^2

// ---------------- helpers ----------------
static __device__ __forceinline__ uint32_t smem_u32(const void* p) {
    uint32_t a;
    asm("{ .reg .u64 t; cvta.to.shared.u64 t, %1; cvt.u32.u64 %0, t; }" : "=r"(a) : "l"(p));
    return a;
}
static __device__ __forceinline__ void cpa16(uint32_t dst, const void* src) {
    asm volatile("cp.async.cg.shared.global [%0], [%1], 16;" :: "r"(dst), "l"(src) : "memory");
}
static __device__ __forceinline__ void cpa_commit() {
    asm volatile("cp.async.commit_group;" ::: "memory");
}
template <int N>
static __device__ __forceinline__ void cpa_wait() {
    asm volatile("cp.async.wait_group %0;" :: "n"(N) : "memory");
}
static __device__ __forceinline__ void ldsm4(uint32_t* r, uint32_t a) {
    asm volatile("ldmatrix.sync.aligned.m8n8.x4.shared.b16 {%0,%1,%2,%3}, [%4];"
                 : "=r"(r[0]), "=r"(r[1]), "=r"(r[2]), "=r"(r[3]) : "r"(a));
}
static __device__ __forceinline__ void imma16832(int* d, const uint32_t* a,
                                                 uint32_t b0, uint32_t b1) {
    asm volatile("mma.sync.aligned.m16n8k32.row.col.s32.s8.s8.s32 "
                 "{%0,%1,%2,%3}, {%4,%5,%6,%7}, {%8,%9}, {%0,%1,%2,%3};"
                 : "+r"(d[0]), "+r"(d[1]), "+r"(d[2]), "+r"(d[3])
                 : "r"(a[0]), "r"(a[1]), "r"(a[2]), "r"(a[3]), "r"(b0), "r"(b1));
}
static __device__ __forceinline__ float sig_f(float x) {
    return __fdividef(1.0f, 1.0f + __expf(-x));
}
static __device__ __forceinline__ float tanh_f(float x) {
    return __fdividef(2.0f, 1.0f + __expf(-2.0f * x)) - 1.0f;
}
// SW64 swizzle for 64B rows: XOR byte-col with ((row>>1)&3)*16
static __device__ __forceinline__ uint32_t sw64(int row, int cb) {
    return (uint32_t)(row * 64 + (cb ^ (((row >> 1) & 3) * 16)));
}

// Load one chunk (A limbs 64x64B, B limbs 64x64B) into a stage via cp.async.
static __device__ __forceinline__ void load_chunk(
    uint32_t st, const int8_t* __restrict__ A1, const int8_t* __restrict__ A2,
    const int8_t* __restrict__ B1, const int8_t* __restrict__ B2,
    int m0, int n0, int koff, int tid)
{
    // Each tile: 64 rows x 4 16B-units = 256 units; 128 threads -> 2 iters per tile
#pragma unroll
    for (int r = 0; r < 2; ++r) {
        int q   = tid + NT * r;
        int row = q >> 2;
        int cb  = (q & 3) * 16;
        uint32_t sw = sw64(row, cb);
        size_t ga = (size_t)(m0 + row) * HID + koff + cb;
        size_t gb = (size_t)(n0 + row) * HID + koff + cb;
        cpa16(st + OFF_A1 + sw, A1 + ga);
        cpa16(st + OFF_A2 + sw, A2 + ga);
        cpa16(st + OFF_B1 + sw, B1 + gb);
        cpa16(st + OFF_B2 + sw, B2 + gb);
    }
}

// ---------------- prep kernels ----------------
__global__ void wquant_kernel(const float* __restrict__ W,
                              int8_t* __restrict__ w1,
                              int8_t* __restrict__ w2,
                              float* __restrict__ ws)
{
    __shared__ float wmax[8];
    int n = blockIdx.x;              // gate-interleaved row: n = 4*j + g
    int j = n >> 2, g = n & 3;
    const float* src = W + ((size_t)g * HID + j) * HID;
    int tid = threadIdx.x;

    float vals[8];
    float amax = 0.0f;
#pragma unroll
    for (int r = 0; r < 8; ++r) {
        float v = src[tid + 256 * r];
        vals[r] = v;
        amax = fmaxf(amax, fabsf(v));
    }
#pragma unroll
    for (int off = 16; off > 0; off >>= 1)
        amax = fmaxf(amax, __shfl_xor_sync(0xffffffffu, amax, off));
    if ((tid & 31) == 0) wmax[tid >> 5] = amax;
    __syncthreads();
    float rmax = fmaxf(fmaxf(fmaxf(wmax[0], wmax[1]), fmaxf(wmax[2], wmax[3])),
                       fmaxf(fmaxf(wmax[4], wmax[5]), fmaxf(wmax[6], wmax[7])));
    float sinv = (rmax > 0.0f) ? (QSCALE / rmax) : 0.0f;

    size_t dst = (size_t)n * HID;
#pragma unroll
    for (int r = 0; r < 8; ++r) {
        int q = __float2int_rn(vals[r] * sinv);
        int l1 = (q + 64) >> 7;
        int l2 = q - (l1 << 7);
        w1[dst + tid + 256 * r] = (int8_t)l1;
        w2[dst + tid + 256 * r] = (int8_t)l2;
    }
    if (tid == 0) ws[n] = rmax / (QSCALE * QSCALE);
}

__global__ void init_kernel(float* __restrict__ cbuf,
                            int8_t* __restrict__ h1,
                            int8_t* __restrict__ h2,
                            float* __restrict__ out,
                            const float* __restrict__ b_lin)
{
    int i = blockIdx.x * blockDim.x + threadIdx.x;
    if (i < BH) {
        cbuf[i] = 0.0f;
        h1[i] = 0; h2[i] = 0;
    }
    if (i < BATCH * TTOT) out[i] = b_lin[0];
}

// ---------------- fused LSTM step: exact int8x2 IMMA (4 products) + cell + pred ----------------
__global__ void __launch_bounds__(NT, 3)
lstm_step(const int8_t* __restrict__ Ah1, const int8_t* __restrict__ Ah2,
          int8_t* __restrict__ Ah1_n, int8_t* __restrict__ Ah2_n,
          float* __restrict__ cbuf,
          const int8_t* __restrict__ W1, const int8_t* __restrict__ W2,
          const float* __restrict__ ws,
          const float* __restrict__ W_ih, const float* __restrict__ b_ih,
          const float* __restrict__ b_hh, const float* __restrict__ W_lin,
          float* __restrict__ out,
          const float* __restrict__ xvec, int xstride, int t)
{
    extern __shared__ char smem_raw[];
    const int tid  = threadIdx.x;
    const int wid  = tid >> 5;
    const int lane = tid & 31;
    const int warp_m = wid & 1;          // 2 x 32 rows
    const int warp_n = wid >> 1;         // 2 x 32 cols
    const int m0 = blockIdx.x * BM;
    const int n0 = blockIdx.y * BN;      // gate-interleaved col base
    const int j0 = n0 >> 2;

    uint32_t sb    = smem_u32(smem_raw);
    uint32_t sbase = (sb + 1023) & ~1023u;
    char*    ctrl  = smem_raw + (sbase - sb);
    uint32_t tiles = sbase + CTRL_B;
    float* bias_s = (float*)(ctrl + 0);      // 64
    float* wih_s  = (float*)(ctrl + 256);    // 64
    float* sgs_s  = (float*)(ctrl + 512);    // 64
    float* rowsum = (float*)(ctrl + 768);    // 64
    float* wlin_s = (float*)(ctrl + 1024);   // 16

    if (tid < 64) {
        int j = j0 + (tid >> 2);
        int g = tid & 3;
        bias_s[tid] = b_ih[g * HID + j] + b_hh[g * HID + j];
        wih_s[tid]  = W_ih[g * HID + j];
        sgs_s[tid]  = ws[n0 + tid];
        rowsum[tid] = 0.0f;
    }
    if (tid < 16) wlin_s[tid] = W_lin[j0 + tid];
    __syncthreads();

    int acc_hi[2][4][4];                 // h1*w1
    int acc_md[2][4][4];                 // h1*w2 + h2*w1
    int acc_lo[2][4][4];                 // h2*w2
#pragma unroll
    for (int i = 0; i < 2; ++i)
#pragma unroll
        for (int jf = 0; jf < 4; ++jf)
#pragma unroll
            for (int kf = 0; kf < 4; ++kf) {
                acc_hi[i][jf][kf] = 0; acc_md[i][jf][kf] = 0; acc_lo[i][jf][kf] = 0;
            }

    // ldmatrix addressing (SW64; xor value is lane-row dependent)
    const int xmA = (((lane & 15) >> 1) & 3) << 4;
    int arow[2];
#pragma unroll
    for (int mf = 0; mf < 2; ++mf)
        arow[mf] = (warp_m * 32 + mf * 16 + (lane & 15)) * 64;
    const int rlB = (lane & 7) + ((lane & 16) ? 8 : 0);
    const int xmB = ((rlB >> 1) & 3) << 4;
    int brow[2];
#pragma unroll
    for (int q = 0; q < 2; ++q)
        brow[q] = (warp_n * 32 + q * 16 + rlB) * 64;
    const int acoladd = (lane & 16) ? 16 : 0;
    const int bcoladd = (lane & 8) ? 16 : 0;

    // Prologue
#pragma unroll
    for (int pc = 0; pc < NSTAGE - 1; ++pc) {
        load_chunk(tiles + pc * STAGE_B, Ah1, Ah2, W1, W2, m0, n0, pc * BK, tid);
        cpa_commit();
    }

    for (int c = 0; c < NCH; ++c) {
        cpa_wait<NSTAGE - 2>();
        __syncthreads();

        {
            int cn = c + NSTAGE - 1;
            if (cn < NCH) {
                load_chunk(tiles + (cn & (NSTAGE - 1)) * STAGE_B, Ah1, Ah2, W1, W2,
                           m0, n0, cn * BK, tid);
            }
            cpa_commit();
        }

        uint32_t st = tiles + (c & (NSTAGE - 1)) * STAGE_B;
#pragma unroll
        for (int kk = 0; kk < 2; ++kk) {           // two k32 slices per 64B row
            uint32_t a1[2][4], a2[2][4], b1[2][4], b2[2][4];
            int colA = kk * 32 + acoladd;
            int colB = kk * 32 + bcoladd;
#pragma unroll
            for (int mf = 0; mf < 2; ++mf) {
                ldsm4(a1[mf], st + OFF_A1 + arow[mf] + (uint32_t)(colA ^ xmA));
                ldsm4(a2[mf], st + OFF_A2 + arow[mf] + (uint32_t)(colA ^ xmA));
            }
#pragma unroll
            for (int q = 0; q < 2; ++q) {
                ldsm4(b1[q], st + OFF_B1 + brow[q] + (uint32_t)(colB ^ xmB));
                ldsm4(b2[q], st + OFF_B2 + brow[q] + (uint32_t)(colB ^ xmB));
            }
#pragma unroll
            for (int mf = 0; mf < 2; ++mf) {
#pragma unroll
                for (int nf = 0; nf < 4; ++nf) {
                    const int q = nf >> 1, p = (nf & 1) * 2;
                    imma16832(acc_hi[mf][nf], a1[mf], b1[q][p], b1[q][p + 1]);
                    imma16832(acc_md[mf][nf], a1[mf], b2[q][p], b2[q][p + 1]);
                    imma16832(acc_md[mf][nf], a2[mf], b1[q][p], b1[q][p + 1]);
                    imma16832(acc_lo[mf][nf], a2[mf], b2[q][p], b2[q][p + 1]);
                }
            }
        }
    }

    // ---- epilogue: gate exchange + LSTM cell + prediction ----
    const bool oddl = (lane & 1);
    const int slot  = (lane >> 1) & 1;
    const int rloc0 = (lane >> 2) + (oddl ? 8 : 0);

#pragma unroll
    for (int mf = 0; mf < 2; ++mf) {
        const int rloc = warp_m * 32 + mf * 16 + rloc0;
        const int m = m0 + rloc;
        const float xin = xvec[(size_t)m * xstride];
        float predp = 0.0f;
#pragma unroll
        for (int nf = 0; nf < 4; ++nf) {
            float c0 = 16384.0f * (float)acc_hi[mf][nf][0] + 128.0f * (float)acc_md[mf][nf][0]
                     + (float)acc_lo[mf][nf][0];
            float c1 = 16384.0f * (float)acc_hi[mf][nf][1] + 128.0f * (float)acc_md[mf][nf][1]
                     + (float)acc_lo[mf][nf][1];
            float c2 = 16384.0f * (float)acc_hi[mf][nf][2] + 128.0f * (float)acc_md[mf][nf][2]
                     + (float)acc_lo[mf][nf][2];
            float c3 = 16384.0f * (float)acc_hi[mf][nf][3] + 128.0f * (float)acc_md[mf][nf][3]
                     + (float)acc_lo[mf][nf][3];
            float t0 = __shfl_xor_sync(0xffffffffu, c0, 1);
            float t1 = __shfl_xor_sync(0xffffffffu, c1, 1);
            float t2 = __shfl_xor_sync(0xffffffffu, c2, 1);
            float t3 = __shfl_xor_sync(0xffffffffu, c3, 1);
            float gi, gf, gg, go;
            if (!oddl) { gi = c0; gf = c1; gg = t0; go = t1; }
            else       { gi = t2; gf = t3; gg = c2; go = c3; }

            const int jl = warp_n * 8 + nf * 2 + slot;
            const int nb = jl * 4;
            gi = sgs_s[nb + 0] * gi + bias_s[nb + 0] + xin * wih_s[nb + 0];
            gf = sgs_s[nb + 1] * gf + bias_s[nb + 1] + xin * wih_s[nb + 1];
            gg = sgs_s[nb + 2] * gg + bias_s[nb + 2] + xin * wih_s[nb + 2];
            go = sgs_s[nb + 3] * go + bias_s[nb + 3] + xin * wih_s[nb + 3];

            const size_t off = (size_t)m * HID + (j0 + jl);
            float cp = cbuf[off];
            float cn = sig_f(gf) * cp + sig_f(gi) * tanh_f(gg);
            cbuf[off] = cn;
            float hn = sig_f(go) * tanh_f(cn);

            int qh = __float2int_rn(hn * QSCALE);
            int l1 = (qh + 64) >> 7;
            int l2 = qh - (l1 << 7);
            Ah1_n[off] = (int8_t)l1;
            Ah2_n[off] = (int8_t)l2;
            predp += hn * wlin_s[jl];
        }
        atomicAdd(&rowsum[rloc], predp);
    }
    __syncthreads();
    if (tid < 64)
        atomicAdd(&out[(size_t)(m0 + tid) * TTOT + t], rowsum[tid]);
}

// ---------------- host launch ----------------
extern "C" void kernel_launch(void* const* d_in, const int* in_sizes, int n_in,
                              void* d_out, int out_size) {
    const float* x     = (const float*)d_in[0];
    const float* W_ih  = (const float*)d_in[1];
    const float* W_hh  = (const float*)d_in[2];
    const float* b_ih  = (const float*)d_in[3];
    const float* b_hh  = (const float*)d_in[4];
    const float* W_lin = (const float*)d_in[5];
    const float* b_lin = (const float*)d_in[6];
    float* out = (float*)d_out;

    float *cbuf, *ws;
    int8_t *h1, *h2, *w1, *w2;
    cudaGetSymbolAddress((void**)&cbuf, g_c);
    cudaGetSymbolAddress((void**)&h1,   g_h1);
    cudaGetSymbolAddress((void**)&h2,   g_h2);
    cudaGetSymbolAddress((void**)&w1,   g_w1);
    cudaGetSymbolAddress((void**)&w2,   g_w2);
    cudaGetSymbolAddress((void**)&ws,   g_ws);

    cudaFuncSetAttribute(lstm_step, cudaFuncAttributeMaxDynamicSharedMemorySize, SMEM_DYN);

    wquant_kernel<<<HID4, 256>>>(W_hh, w1, w2, ws);
    init_kernel<<<(BH + 255) / 256, 256>>>(cbuf, h1, h2, out, b_lin);

    dim3 grid(BATCH / BM, HID4 / BN);

    for (int t = 0; t < TTOT; ++t) {
        const int cur = t & 1;
        const float* xvec;
        int xstride;
        if (t < TOBS) { xvec = x + t;         xstride = TOBS; }
        else          { xvec = out + (t - 1); xstride = TTOT; }

        lstm_step<<<grid, NT, SMEM_DYN>>>(
            h1 + (size_t)cur * BH, h2 + (size_t)cur * BH,
            h1 + (size_t)(1 - cur) * BH, h2 + (size_t)(1 - cur) * BH,
            cbuf, w1, w2, ws,
            W_ih, b_ih, b_hh, W_lin,
            out, xvec, xstride, t);
    }
}

// round 13
// speedup vs baseline: 2.6536x; 2.6536x over previous
#include <cuda_runtime.h>
#include <cuda_bf16.h>
#include <cstdint>

#define BATCH 256
#define TOBS  80
#define TTOT  160
#define HID   2048
#define HID4  8192
#define BH    (BATCH * HID)

#define NT      256                  // 8 warps: warp_m (2) x warp_n (4), warp tile 32x32
#define BM      64
#define BN      128
#define BK      64                   // K elements per chunk (bf16) = 128 bytes/row
#define NCH     64                   // 32 phase1 (Ahi+Alo vs Whi) + 32 phase2 (Ahi vs Wlo)
#define NSTAGE  3
#define OFF_AHI 0
#define OFF_ALO 8192
#define OFF_B   16384
#define STAGE_B 32768                // Ahi 8K + Alo 8K + B 16K
#define CTRL_B  2048
#define SMEM_DYN (1024 + CTRL_B + NSTAGE * STAGE_B)

// ---------------- persistent device state ----------------
__device__ float          g_c[BH];
__device__ __nv_bfloat16  g_hhi[2 * BH];
__device__ __nv_bfloat16  g_hlo[2 * BH];
__device__ __nv_bfloat16  g_whi[(size_t)HID4 * HID];   // gate-interleaved W_hh hi
__device__ __nv_bfloat16  g_wlo[(size_t)HID4 * HID];   // gate-interleaved W_hh lo

// ---------------- helpers ----------------
static __device__ __forceinline__ uint32_t smem_u32(const void* p) {
    uint32_t a;
    asm("{ .reg .u64 t; cvta.to.shared.u64 t, %1; cvt.u32.u64 %0, t; }" : "=r"(a) : "l"(p));
    return a;
}
static __device__ __forceinline__ void cpa16(uint32_t dst, const void* src) {
    asm volatile("cp.async.cg.shared.global [%0], [%1], 16;" :: "r"(dst), "l"(src) : "memory");
}
static __device__ __forceinline__ void cpa_commit() {
    asm volatile("cp.async.commit_group;" ::: "memory");
}
template <int N>
static __device__ __forceinline__ void cpa_wait() {
    asm volatile("cp.async.wait_group %0;" :: "n"(N) : "memory");
}
static __device__ __forceinline__ void ldsm4(uint32_t* r, uint32_t a) {
    asm volatile("ldmatrix.sync.aligned.m8n8.x4.shared.b16 {%0,%1,%2,%3}, [%4];"
                 : "=r"(r[0]), "=r"(r[1]), "=r"(r[2]), "=r"(r[3]) : "r"(a));
}
static __device__ __forceinline__ void mma16816(float* d, const uint32_t* a, const uint32_t* b) {
    asm volatile("mma.sync.aligned.m16n8k16.row.col.f32.bf16.bf16.f32 "
                 "{%0,%1,%2,%3}, {%4,%5,%6,%7}, {%8,%9}, {%0,%1,%2,%3};"
                 : "+f"(d[0]), "+f"(d[1]), "+f"(d[2]), "+f"(d[3])
                 : "r"(a[0]), "r"(a[1]), "r"(a[2]), "r"(a[3]), "r"(b[0]), "r"(b[1]));
}
static __device__ __forceinline__ float sig_f(float x) {
    return __fdividef(1.0f, 1.0f + __expf(-x));
}
static __device__ __forceinline__ float tanh_f(float x) {
    return __fdividef(2.0f, 1.0f + __expf(-2.0f * x)) - 1.0f;
}

// Load one chunk into a stage via cp.async, SW128.
// Phase1 (withAlo): Ahi + Alo + B(Whi). Phase2: Ahi + B(Wlo).
static __device__ __forceinline__ void load_chunk(
    uint32_t st, const __nv_bfloat16* __restrict__ Ahi, const __nv_bfloat16* __restrict__ Alo,
    const __nv_bfloat16* __restrict__ B,
    int m0, int n0, int koff, int tid, bool withAlo)
{
    // A tiles: 64 rows * 8 16B-units = 512 units; 256 threads -> 2 iters
#pragma unroll
    for (int r = 0; r < 2; ++r) {
        int q   = tid + NT * r;
        int row = q >> 3;
        int cb  = (q & 7) * 16;
        uint32_t sw = (uint32_t)(row * 128) + (uint32_t)(cb ^ ((row & 7) * 16));
        const char* ga = (const char*)(Ahi + (size_t)(m0 + row) * HID + koff) + cb;
        cpa16(st + OFF_AHI + sw, ga);
        if (withAlo) {
            const char* gl = (const char*)(Alo + (size_t)(m0 + row) * HID + koff) + cb;
            cpa16(st + OFF_ALO + sw, gl);
        }
    }
    // B tile: 128 rows * 8 = 1024 units -> 4 iters
#pragma unroll
    for (int r = 0; r < 4; ++r) {
        int q   = tid + NT * r;
        int row = q >> 3;
        int cb  = (q & 7) * 16;
        uint32_t sw = (uint32_t)(row * 128) + (uint32_t)(cb ^ ((row & 7) * 16));
        const char* gb = (const char*)(B + (size_t)(n0 + row) * HID + koff) + cb;
        cpa16(st + OFF_B + sw, gb);
    }
}

// Compute one chunk: acc += Ahi*B (+ Alo*B if withAlo)
static __device__ __forceinline__ void compute_chunk(
    uint32_t st, float (&acc)[2][4][4],
    const int* arow, const int* brow, int xm, int acoladd, int bcoladd, bool withAlo)
{
#pragma unroll
    for (int kk = 0; kk < 4; ++kk) {
        uint32_t ahi[2][4], alo[2][4], b[2][4];
        int colA = kk * 32 + acoladd;
        int colB = kk * 32 + bcoladd;
#pragma unroll
        for (int mf = 0; mf < 2; ++mf)
            ldsm4(ahi[mf], st + OFF_AHI + arow[mf] + (uint32_t)(colA ^ xm));
#pragma unroll
        for (int q = 0; q < 2; ++q)
            ldsm4(b[q], st + OFF_B + brow[q] + (uint32_t)(colB ^ xm));
        if (withAlo) {
#pragma unroll
            for (int mf = 0; mf < 2; ++mf)
                ldsm4(alo[mf], st + OFF_ALO + arow[mf] + (uint32_t)(colA ^ xm));
        }
#pragma unroll
        for (int mf = 0; mf < 2; ++mf) {
#pragma unroll
            for (int nf = 0; nf < 4; ++nf) {
                const uint32_t bp[2] = { b[nf >> 1][(nf & 1) * 2],
                                         b[nf >> 1][(nf & 1) * 2 + 1] };
                mma16816(acc[mf][nf], ahi[mf], bp);
                if (withAlo) mma16816(acc[mf][nf], alo[mf], bp);
            }
        }
    }
}

// ---------------- prep kernels ----------------
__global__ void wconv_kernel(const float* __restrict__ W,
                             __nv_bfloat16* __restrict__ whi,
                             __nv_bfloat16* __restrict__ wlo)
{
    int n = blockIdx.x;                  // gate-interleaved row: n = 4*j + g
    int j = n >> 2, g = n & 3;
    const float4* src = (const float4*)(W + ((size_t)g * HID + j) * HID);
    size_t dst = (size_t)n * HID;
#pragma unroll
    for (int r = 0; r < 2; ++r) {
        int q = threadIdx.x + 256 * r;
        float4 v = src[q];
        int k = q * 4;
        float xs[4] = {v.x, v.y, v.z, v.w};
#pragma unroll
        for (int c = 0; c < 4; ++c) {
            __nv_bfloat16 hi = __float2bfloat16(xs[c]);
            whi[dst + k + c] = hi;
            wlo[dst + k + c] = __float2bfloat16(xs[c] - __bfloat162float(hi));
        }
    }
}

__global__ void init_kernel(float* __restrict__ cbuf,
                            __nv_bfloat16* __restrict__ h0hi,
                            __nv_bfloat16* __restrict__ h0lo,
                            float* __restrict__ out,
                            const float* __restrict__ b_lin)
{
    int i = blockIdx.x * blockDim.x + threadIdx.x;
    if (i < BH) {
        cbuf[i] = 0.0f;
        h0hi[i] = __float2bfloat16(0.0f);
        h0lo[i] = __float2bfloat16(0.0f);
    }
    if (i < BATCH * TTOT) out[i] = b_lin[0];
}

// ---------------- fused LSTM step: bf16x3 (B-reuse schedule) + cell + pred ----------------
__global__ void __launch_bounds__(NT, 2)
lstm_step(const __nv_bfloat16* __restrict__ Ahi, const __nv_bfloat16* __restrict__ Alo,
          __nv_bfloat16* __restrict__ Ahi_n, __nv_bfloat16* __restrict__ Alo_n,
          float* __restrict__ cbuf,
          const __nv_bfloat16* __restrict__ Whi, const __nv_bfloat16* __restrict__ Wlo,
          const float* __restrict__ W_ih, const float* __restrict__ b_ih,
          const float* __restrict__ b_hh, const float* __restrict__ W_lin,
          float* __restrict__ out,
          const float* __restrict__ xvec, int xstride, int t)
{
    extern __shared__ char smem_raw[];
    const int tid  = threadIdx.x;
    const int wid  = tid >> 5;
    const int lane = tid & 31;
    const int warp_m = wid & 1;          // 2 x 32 rows
    const int warp_n = wid >> 1;         // 4 x 32 cols
    const int m0 = blockIdx.x * BM;
    const int n0 = blockIdx.y * BN;      // gate-interleaved col base
    const int j0 = n0 >> 2;

    uint32_t sb    = smem_u32(smem_raw);
    uint32_t sbase = (sb + 1023) & ~1023u;
    char*    ctrl  = smem_raw + (sbase - sb);
    uint32_t tiles = sbase + CTRL_B;
    float* bias_s = (float*)(ctrl + 0);      // 128
    float* wih_s  = (float*)(ctrl + 512);    // 128
    float* rowsum = (float*)(ctrl + 1024);   // 64
    float* wlin_s = (float*)(ctrl + 1536);   // 32

    if (tid < 128) {
        int j = j0 + (tid >> 2);
        int g = tid & 3;
        bias_s[tid] = b_ih[g * HID + j] + b_hh[g * HID + j];
        wih_s[tid]  = W_ih[g * HID + j];
    }
    if (tid < 64) rowsum[tid] = 0.0f;
    if (tid < 32) wlin_s[tid] = W_lin[j0 + tid];
    __syncthreads();

    float acc[2][4][4];
#pragma unroll
    for (int i = 0; i < 2; ++i)
#pragma unroll
        for (int jf = 0; jf < 4; ++jf)
#pragma unroll
            for (int kf = 0; kf < 4; ++kf) acc[i][jf][kf] = 0.0f;

    // ldmatrix addressing (SW128: xor (row&7)*16, row-invariant per lane)
    const int xm = (lane & 7) * 16;
    int arow[2], brow[2];
#pragma unroll
    for (int mf = 0; mf < 2; ++mf)
        arow[mf] = (warp_m * 32 + mf * 16 + (lane & 15)) * 128;
#pragma unroll
    for (int q = 0; q < 2; ++q)
        brow[q] = (warp_n * 32 + q * 16 + (lane & 7) + ((lane & 16) ? 8 : 0)) * 128;
    const int acoladd = (lane & 16) ? 16 : 0;
    const int bcoladd = (lane & 8) ? 16 : 0;

    // Prologue: chunks 0,1 (phase1)
    load_chunk(tiles + 0 * STAGE_B, Ahi, Alo, Whi, m0, n0, 0 * BK, tid, true);
    cpa_commit();
    load_chunk(tiles + 1 * STAGE_B, Ahi, Alo, Whi, m0, n0, 1 * BK, tid, true);
    cpa_commit();

    for (int c = 0; c < NCH; ++c) {
        cpa_wait<1>();
        __syncthreads();

        {
            int cn = c + 2;
            if (cn < NCH) {
                int k   = cn & 31;
                bool p1 = (cn < 32);
                load_chunk(tiles + (cn % NSTAGE) * STAGE_B,
                           Ahi, Alo, p1 ? Whi : Wlo,
                           m0, n0, k * BK, tid, p1);
            }
            cpa_commit();   // commit unconditionally to keep group accounting uniform
        }

        uint32_t st = tiles + (c % NSTAGE) * STAGE_B;
        compute_chunk(st, acc, arow, brow, xm, acoladd, bcoladd, c < 32);
    }

    // ---- epilogue: gate exchange + LSTM cell + prediction ----
    const bool oddl = (lane & 1);
    const int slot  = (lane >> 1) & 1;
    const int rloc0 = warp_m * 32 + (lane >> 2) + (oddl ? 8 : 0);

#pragma unroll
    for (int mf = 0; mf < 2; ++mf) {
        const int rloc = rloc0 + mf * 16;
        const int m = m0 + rloc;
        const float xin = xvec[(size_t)m * xstride];
        float predp = 0.0f;
#pragma unroll
        for (int nf = 0; nf < 4; ++nf) {
            float c0 = acc[mf][nf][0], c1 = acc[mf][nf][1];
            float c2 = acc[mf][nf][2], c3 = acc[mf][nf][3];
            float t0 = __shfl_xor_sync(0xffffffffu, c0, 1);
            float t1 = __shfl_xor_sync(0xffffffffu, c1, 1);
            float t2 = __shfl_xor_sync(0xffffffffu, c2, 1);
            float t3 = __shfl_xor_sync(0xffffffffu, c3, 1);
            float gi, gf, gg, go;
            if (!oddl) { gi = c0; gf = c1; gg = t0; go = t1; }
            else       { gi = t2; gf = t3; gg = c2; go = c3; }

            const int jl = warp_n * 8 + nf * 2 + slot;
            const int nb = jl * 4;
            gi += bias_s[nb + 0] + xin * wih_s[nb + 0];
            gf += bias_s[nb + 1] + xin * wih_s[nb + 1];
            gg += bias_s[nb + 2] + xin * wih_s[nb + 2];
            go += bias_s[nb + 3] + xin * wih_s[nb + 3];

            const size_t off = (size_t)m * HID + (j0 + jl);
            float cp = cbuf[off];
            float cn = sig_f(gf) * cp + sig_f(gi) * tanh_f(gg);
            cbuf[off] = cn;
            float hn = sig_f(go) * tanh_f(cn);

            __nv_bfloat16 hi = __float2bfloat16(hn);
            Ahi_n[off] = hi;
            Alo_n[off] = __float2bfloat16(hn - __bfloat162float(hi));
            predp += hn * wlin_s[jl];
        }
        atomicAdd(&rowsum[rloc], predp);
    }
    __syncthreads();
    if (tid < 64)
        atomicAdd(&out[(size_t)(m0 + tid) * TTOT + t], rowsum[tid]);
}

// ---------------- host launch ----------------
extern "C" void kernel_launch(void* const* d_in, const int* in_sizes, int n_in,
                              void* d_out, int out_size) {
    const float* x     = (const float*)d_in[0];
    const float* W_ih  = (const float*)d_in[1];
    const float* W_hh  = (const float*)d_in[2];
    const float* b_ih  = (const float*)d_in[3];
    const float* b_hh  = (const float*)d_in[4];
    const float* W_lin = (const float*)d_in[5];
    const float* b_lin = (const float*)d_in[6];
    float* out = (float*)d_out;

    float *cbuf;
    __nv_bfloat16 *hhi, *hlo, *whi, *wlo;
    cudaGetSymbolAddress((void**)&cbuf, g_c);
    cudaGetSymbolAddress((void**)&hhi,  g_hhi);
    cudaGetSymbolAddress((void**)&hlo,  g_hlo);
    cudaGetSymbolAddress((void**)&whi,  g_whi);
    cudaGetSymbolAddress((void**)&wlo,  g_wlo);

    cudaFuncSetAttribute(lstm_step, cudaFuncAttributeMaxDynamicSharedMemorySize, SMEM_DYN);

    wconv_kernel<<<HID4, 256>>>(W_hh, whi, wlo);
    init_kernel<<<(BH + 255) / 256, 256>>>(cbuf, hhi, hlo, out, b_lin);

    dim3 grid(BATCH / BM, HID4 / BN);

    for (int t = 0; t < TTOT; ++t) {
        const int cur = t & 1;
        const float* xvec;
        int xstride;
        if (t < TOBS) { xvec = x + t;         xstride = TOBS; }
        else          { xvec = out + (t - 1); xstride = TTOT; }

        lstm_step<<<grid, NT, SMEM_DYN>>>(
            hhi + (size_t)cur * BH, hlo + (size_t)cur * BH,
            hhi + (size_t)(1 - cur) * BH, hlo + (size_t)(1 - cur) * BH,
            cbuf, whi, wlo,
            W_ih, b_ih, b_hh, W_lin,
            out, xvec, xstride, t);
    }
}

// round 14
// speedup vs baseline: 2.9367x; 1.1067x over previous
#include <cuda_runtime.h>
#include <cuda_bf16.h>
#include <cstdint>

#define BATCH 256
#define TOBS  80
#define TTOT  160
#define HID   2048
#define HID4  8192
#define BH    (BATCH * HID)

#define NT      256                  // 8 warps: warp_m (2) x warp_n (4), warp tile 32x32
#define BM      64
#define BN      128
#define NSUP    48                   // super-chunks: K=128 each, 3 products x 16
#define SUB_A1  0
#define SUB_A2  8192
#define SUB_B1  16384
#define SUB_B2  32768
#define SUPER_B 49152                // 8+8+16+16 KB
#define CTRL_B  2048
#define SMEM_DYN (1024 + CTRL_B + 2 * SUPER_B)

// ---------------- persistent device state ----------------
__device__ float          g_c[BH];
__device__ __nv_bfloat16  g_hhi[2 * BH];
__device__ __nv_bfloat16  g_hlo[2 * BH];
__device__ __nv_bfloat16  g_whi[(size_t)HID4 * HID];   // gate-interleaved W_hh hi
__device__ __nv_bfloat16  g_wlo[(size_t)HID4 * HID];   // gate-interleaved W_hh lo

// ---------------- helpers ----------------
static __device__ __forceinline__ uint32_t smem_u32(const void* p) {
    uint32_t a;
    asm("{ .reg .u64 t; cvta.to.shared.u64 t, %1; cvt.u32.u64 %0, t; }" : "=r"(a) : "l"(p));
    return a;
}
static __device__ __forceinline__ void cpa16(uint32_t dst, const void* src) {
    asm volatile("cp.async.cg.shared.global [%0], [%1], 16;" :: "r"(dst), "l"(src) : "memory");
}
static __device__ __forceinline__ void cpa_commit() {
    asm volatile("cp.async.commit_group;" ::: "memory");
}
template <int N>
static __device__ __forceinline__ void cpa_wait() {
    asm volatile("cp.async.wait_group %0;" :: "n"(N) : "memory");
}
static __device__ __forceinline__ void ldsm4(uint32_t* r, uint32_t a) {
    asm volatile("ldmatrix.sync.aligned.m8n8.x4.shared.b16 {%0,%1,%2,%3}, [%4];"
                 : "=r"(r[0]), "=r"(r[1]), "=r"(r[2]), "=r"(r[3]) : "r"(a));
}
static __device__ __forceinline__ void mma16816(float* d, const uint32_t* a, const uint32_t* b) {
    asm volatile("mma.sync.aligned.m16n8k16.row.col.f32.bf16.bf16.f32 "
                 "{%0,%1,%2,%3}, {%4,%5,%6,%7}, {%8,%9}, {%0,%1,%2,%3};"
                 : "+f"(d[0]), "+f"(d[1]), "+f"(d[2]), "+f"(d[3])
                 : "r"(a[0]), "r"(a[1]), "r"(a[2]), "r"(a[3]), "r"(b[0]), "r"(b[1]));
}
static __device__ __forceinline__ float sig_f(float x) {
    return __fdividef(1.0f, 1.0f + __expf(-x));
}
static __device__ __forceinline__ float tanh_f(float x) {
    return __fdividef(2.0f, 1.0f + __expf(-2.0f * x)) - 1.0f;
}

// ---------------- prep kernels ----------------
__global__ void wconv_kernel(const float* __restrict__ W,
                             __nv_bfloat16* __restrict__ whi,
                             __nv_bfloat16* __restrict__ wlo)
{
    int n = blockIdx.x;                  // gate-interleaved row: n = 4*j + g
    int j = n >> 2, g = n & 3;
    const float4* src = (const float4*)(W + ((size_t)g * HID + j) * HID);
    size_t dst = (size_t)n * HID;
#pragma unroll
    for (int r = 0; r < 2; ++r) {
        int q = threadIdx.x + 256 * r;
        float4 v = src[q];
        int k = q * 4;
        float xs[4] = {v.x, v.y, v.z, v.w};
#pragma unroll
        for (int c = 0; c < 4; ++c) {
            __nv_bfloat16 hi = __float2bfloat16(xs[c]);
            whi[dst + k + c] = hi;
            wlo[dst + k + c] = __float2bfloat16(xs[c] - __bfloat162float(hi));
        }
    }
}

__global__ void init_kernel(float* __restrict__ cbuf,
                            __nv_bfloat16* __restrict__ h0hi,
                            __nv_bfloat16* __restrict__ h0lo,
                            float* __restrict__ out,
                            const float* __restrict__ b_lin)
{
    int i = blockIdx.x * blockDim.x + threadIdx.x;
    if (i < BH) {
        cbuf[i] = 0.0f;
        h0hi[i] = __float2bfloat16(0.0f);
        h0lo[i] = __float2bfloat16(0.0f);
    }
    if (i < BATCH * TTOT) out[i] = b_lin[0];
}

// ---------------- fused LSTM step: bf16x3, K=128 super-chunks, 2-stage ----------------
__global__ void __launch_bounds__(NT, 2)
lstm_step(const __nv_bfloat16* __restrict__ Ahi, const __nv_bfloat16* __restrict__ Alo,
          __nv_bfloat16* __restrict__ Ahi_n, __nv_bfloat16* __restrict__ Alo_n,
          float* __restrict__ cbuf,
          const __nv_bfloat16* __restrict__ Whi, const __nv_bfloat16* __restrict__ Wlo,
          const float* __restrict__ W_ih, const float* __restrict__ b_ih,
          const float* __restrict__ b_hh, const float* __restrict__ W_lin,
          float* __restrict__ out,
          const float* __restrict__ xvec, int xstride, int t)
{
    extern __shared__ char smem_raw[];
    const int tid  = threadIdx.x;
    const int wid  = tid >> 5;
    const int lane = tid & 31;
    const int warp_m = wid & 1;          // 2 x 32 rows
    const int warp_n = wid >> 1;         // 4 x 32 cols
    const int m0 = blockIdx.x * BM;
    const int n0 = blockIdx.y * BN;      // gate-interleaved col base
    const int j0 = n0 >> 2;

    uint32_t sb    = smem_u32(smem_raw);
    uint32_t sbase = (sb + 1023) & ~1023u;
    char*    ctrl  = smem_raw + (sbase - sb);
    uint32_t tiles = sbase + CTRL_B;
    float* bias_s = (float*)(ctrl + 0);      // 128
    float* wih_s  = (float*)(ctrl + 512);    // 128
    float* rowsum = (float*)(ctrl + 1024);   // 64
    float* wlin_s = (float*)(ctrl + 1536);   // 32

    if (tid < 128) {
        int j = j0 + (tid >> 2);
        int g = tid & 3;
        bias_s[tid] = b_ih[g * HID + j] + b_hh[g * HID + j];
        wih_s[tid]  = W_ih[g * HID + j];
    }
    if (tid < 64) rowsum[tid] = 0.0f;
    if (tid < 32) wlin_s[tid] = W_lin[j0 + tid];
    __syncthreads();

    // ---- hoisted per-thread load addressing (byte offsets) ----
    uint32_t swA[2], aoff[2];            // A: 64 rows x 8 16B units = 512; 2 iters
#pragma unroll
    for (int r = 0; r < 2; ++r) {
        int q   = tid + NT * r;
        int row = q >> 3;
        int cb  = (q & 7) * 16;
        swA[r]  = (uint32_t)(row * 128 + (cb ^ ((row & 7) * 16)));
        aoff[r] = (uint32_t)(((m0 + row) * HID) * 2 + cb);
    }
    uint32_t swB[4], boff[4];            // B: 128 rows x 8 = 1024; 4 iters
#pragma unroll
    for (int r = 0; r < 4; ++r) {
        int q   = tid + NT * r;
        int row = q >> 3;
        int cb  = (q & 7) * 16;
        swB[r]  = (uint32_t)(row * 128 + (cb ^ ((row & 7) * 16)));
        boff[r] = (uint32_t)(((n0 + row) * HID) * 2 + cb);
    }

    float acc[2][4][4];
#pragma unroll
    for (int i = 0; i < 2; ++i)
#pragma unroll
        for (int jf = 0; jf < 4; ++jf)
#pragma unroll
            for (int kf = 0; kf < 4; ++kf) acc[i][jf][kf] = 0.0f;

    // ldmatrix addressing (SW128: xor (row&7)*16, row-invariant per lane)
    const int xm = (lane & 7) * 16;
    int arow[2], brow[2];
#pragma unroll
    for (int mf = 0; mf < 2; ++mf)
        arow[mf] = (warp_m * 32 + mf * 16 + (lane & 15)) * 128;
#pragma unroll
    for (int q = 0; q < 2; ++q)
        brow[q] = (warp_n * 32 + q * 16 + (lane & 7) + ((lane & 16) ? 8 : 0)) * 128;
    const int acoladd = (lane & 16) ? 16 : 0;
    const int bcoladd = (lane & 8) ? 16 : 0;

    // ---- load one super-chunk (K=128 = two 64-K subtiles) into a stage ----
    auto load_super = [&](uint32_t st, const char* Ab, const char* Bb, uint32_t koffB) {
#pragma unroll
        for (int r = 0; r < 2; ++r) {
            cpa16(st + SUB_A1 + swA[r], Ab + aoff[r] + koffB);
            cpa16(st + SUB_A2 + swA[r], Ab + aoff[r] + koffB + 128);
        }
#pragma unroll
        for (int r = 0; r < 4; ++r) {
            cpa16(st + SUB_B1 + swB[r], Bb + boff[r] + koffB);
            cpa16(st + SUB_B2 + swB[r], Bb + boff[r] + koffB + 128);
        }
    };

    // ---- compute one 64-K subtile ----
    auto compute_sub = [&](uint32_t sta, uint32_t stb) {
#pragma unroll
        for (int kk = 0; kk < 4; ++kk) {
            uint32_t a[2][4], b[2][4];
            int colA = kk * 32 + acoladd;
            int colB = kk * 32 + bcoladd;
#pragma unroll
            for (int mf = 0; mf < 2; ++mf)
                ldsm4(a[mf], sta + arow[mf] + (uint32_t)(colA ^ xm));
#pragma unroll
            for (int q = 0; q < 2; ++q)
                ldsm4(b[q], stb + brow[q] + (uint32_t)(colB ^ xm));
#pragma unroll
            for (int mf = 0; mf < 2; ++mf) {
#pragma unroll
                for (int nf = 0; nf < 4; ++nf) {
                    const uint32_t bp[2] = { b[nf >> 1][(nf & 1) * 2],
                                             b[nf >> 1][(nf & 1) * 2 + 1] };
                    mma16816(acc[mf][nf], a[mf], bp);
                }
            }
        }
    };

    const char* AhiB = (const char*)Ahi;
    const char* AloB = (const char*)Alo;
    const char* WhiB = (const char*)Whi;
    const char* WloB = (const char*)Wlo;

    // Prologue: super-chunk 0 (product 0: Ahi x Whi) into stage 0
    load_super(tiles, AhiB, WhiB, 0);
    cpa_commit();

    for (int c = 0; c < NSUP; ++c) {
        cpa_wait<0>();
        __syncthreads();

        int cn = c + 1;
        if (cn < NSUP) {
            int p = cn >> 4;                       // 0: AhiWhi, 1: AhiWlo, 2: AloWhi
            const char* Ab = (p == 2) ? AloB : AhiB;
            const char* Bb = (p == 1) ? WloB : WhiB;
            load_super(tiles + (uint32_t)(cn & 1) * SUPER_B, Ab, Bb,
                       (uint32_t)(cn & 15) * 256);
        }
        cpa_commit();

        uint32_t st = tiles + (uint32_t)(c & 1) * SUPER_B;
        compute_sub(st + SUB_A1, st + SUB_B1);
        compute_sub(st + SUB_A2, st + SUB_B2);
    }

    // ---- epilogue: gate exchange + LSTM cell + prediction ----
    const bool oddl = (lane & 1);
    const int slot  = (lane >> 1) & 1;
    const int rloc0 = warp_m * 32 + (lane >> 2) + (oddl ? 8 : 0);

#pragma unroll
    for (int mf = 0; mf < 2; ++mf) {
        const int rloc = rloc0 + mf * 16;
        const int m = m0 + rloc;
        const float xin = xvec[(size_t)m * xstride];
        float predp = 0.0f;
#pragma unroll
        for (int nf = 0; nf < 4; ++nf) {
            float c0 = acc[mf][nf][0], c1 = acc[mf][nf][1];
            float c2 = acc[mf][nf][2], c3 = acc[mf][nf][3];
            float t0 = __shfl_xor_sync(0xffffffffu, c0, 1);
            float t1 = __shfl_xor_sync(0xffffffffu, c1, 1);
            float t2 = __shfl_xor_sync(0xffffffffu, c2, 1);
            float t3 = __shfl_xor_sync(0xffffffffu, c3, 1);
            float gi, gf, gg, go;
            if (!oddl) { gi = c0; gf = c1; gg = t0; go = t1; }
            else       { gi = t2; gf = t3; gg = c2; go = c3; }

            const int jl = warp_n * 8 + nf * 2 + slot;
            const int nb = jl * 4;
            gi += bias_s[nb + 0] + xin * wih_s[nb + 0];
            gf += bias_s[nb + 1] + xin * wih_s[nb + 1];
            gg += bias_s[nb + 2] + xin * wih_s[nb + 2];
            go += bias_s[nb + 3] + xin * wih_s[nb + 3];

            const size_t off = (size_t)m * HID + (j0 + jl);
            float cp = cbuf[off];
            float cn = sig_f(gf) * cp + sig_f(gi) * tanh_f(gg);
            cbuf[off] = cn;
            float hn = sig_f(go) * tanh_f(cn);

            __nv_bfloat16 hi = __float2bfloat16(hn);
            Ahi_n[off] = hi;
            Alo_n[off] = __float2bfloat16(hn - __bfloat162float(hi));
            predp += hn * wlin_s[jl];
        }
        atomicAdd(&rowsum[rloc], predp);
    }
    __syncthreads();
    if (tid < 64)
        atomicAdd(&out[(size_t)(m0 + tid) * TTOT + t], rowsum[tid]);
}

// ---------------- host launch ----------------
extern "C" void kernel_launch(void* const* d_in, const int* in_sizes, int n_in,
                              void* d_out, int out_size) {
    const float* x     = (const float*)d_in[0];
    const float* W_ih  = (const float*)d_in[1];
    const float* W_hh  = (const float*)d_in[2];
    const float* b_ih  = (const float*)d_in[3];
    const float* b_hh  = (const float*)d_in[4];
    const float* W_lin = (const float*)d_in[5];
    const float* b_lin = (const float*)d_in[6];
    float* out = (float*)d_out;

    float *cbuf;
    __nv_bfloat16 *hhi, *hlo, *whi, *wlo;
    cudaGetSymbolAddress((void**)&cbuf, g_c);
    cudaGetSymbolAddress((void**)&hhi,  g_hhi);
    cudaGetSymbolAddress((void**)&hlo,  g_hlo);
    cudaGetSymbolAddress((void**)&whi,  g_whi);
    cudaGetSymbolAddress((void**)&wlo,  g_wlo);

    cudaFuncSetAttribute(lstm_step, cudaFuncAttributeMaxDynamicSharedMemorySize, SMEM_DYN);

    wconv_kernel<<<HID4, 256>>>(W_hh, whi, wlo);
    init_kernel<<<(BH + 255) / 256, 256>>>(cbuf, hhi, hlo, out, b_lin);

    dim3 grid(BATCH / BM, HID4 / BN);

    for (int t = 0; t < TTOT; ++t) {
        const int cur = t & 1;
        const float* xvec;
        int xstride;
        if (t < TOBS) { xvec = x + t;         xstride = TOBS; }
        else          { xvec = out + (t - 1); xstride = TTOT; }

        lstm_step<<<grid, NT, SMEM_DYN>>>(
            hhi + (size_t)cur * BH, hlo + (size_t)cur * BH,
            hhi + (size_t)(1 - cur) * BH, hlo + (size_t)(1 - cur) * BH,
            cbuf, whi, wlo,
            W_ih, b_ih, b_hh, W_lin,
            out, xvec, xstride, t);
    }
}

// round 15
// speedup vs baseline: 3.3267x; 1.1328x over previous
#include <cuda_runtime.h>
#include <cuda_bf16.h>
#include <cstdint>

#define BATCH 256
#define TOBS  80
#define TTOT  160
#define HID   2048
#define HID4  8192
#define BH    (BATCH * HID)

#define NT      256                  // 8 warps: warp_m (2) x warp_n (4), warp tile 32x32
#define BM      64
#define BN      128
#define NSUP    48                   // super-chunks: K=128 each, 3 products x 16
#define SUB_A1  0
#define SUB_A2  8192
#define SUB_B1  16384
#define SUB_B2  32768
#define SUPER_B 49152                // 8+8+16+16 KB
#define CTRL_B  2048
#define SMEM_DYN (1024 + CTRL_B + 2 * SUPER_B)

// ---------------- persistent device state ----------------
__device__ float          g_c[BH];
__device__ __nv_bfloat16  g_hhi[2 * BH];
__device__ __nv_bfloat16  g_hlo[2 * BH];
__device__ __nv_bfloat16  g_whi[(size_t)HID4 * HID];   // gate-interleaved W_hh hi
__device__ __nv_bfloat16  g_wlo[(size_t)HID4 * HID];   // gate-interleaved W_hh lo

// ---------------- helpers ----------------
static __device__ __forceinline__ uint32_t smem_u32(const void* p) {
    uint32_t a;
    asm("{ .reg .u64 t; cvta.to.shared.u64 t, %1; cvt.u32.u64 %0, t; }" : "=r"(a) : "l"(p));
    return a;
}
static __device__ __forceinline__ void cpa16(uint32_t dst, const void* src) {
    asm volatile("cp.async.cg.shared.global [%0], [%1], 16;" :: "r"(dst), "l"(src) : "memory");
}
static __device__ __forceinline__ void cpa_commit() {
    asm volatile("cp.async.commit_group;" ::: "memory");
}
template <int N>
static __device__ __forceinline__ void cpa_wait() {
    asm volatile("cp.async.wait_group %0;" :: "n"(N) : "memory");
}
static __device__ __forceinline__ void ldsm4(uint32_t* r, uint32_t a) {
    asm volatile("ldmatrix.sync.aligned.m8n8.x4.shared.b16 {%0,%1,%2,%3}, [%4];"
                 : "=r"(r[0]), "=r"(r[1]), "=r"(r[2]), "=r"(r[3]) : "r"(a));
}
static __device__ __forceinline__ void mma16816(float* d, const uint32_t* a, const uint32_t* b) {
    asm volatile("mma.sync.aligned.m16n8k16.row.col.f32.bf16.bf16.f32 "
                 "{%0,%1,%2,%3}, {%4,%5,%6,%7}, {%8,%9}, {%0,%1,%2,%3};"
                 : "+f"(d[0]), "+f"(d[1]), "+f"(d[2]), "+f"(d[3])
                 : "r"(a[0]), "r"(a[1]), "r"(a[2]), "r"(a[3]), "r"(b[0]), "r"(b[1]));
}
static __device__ __forceinline__ float sig_f(float x) {
    return __fdividef(1.0f, 1.0f + __expf(-x));
}
static __device__ __forceinline__ float tanh_f(float x) {
    return __fdividef(2.0f, 1.0f + __expf(-2.0f * x)) - 1.0f;
}

// ---------------- prep kernels ----------------
__global__ void wconv_kernel(const float* __restrict__ W,
                             __nv_bfloat16* __restrict__ whi,
                             __nv_bfloat16* __restrict__ wlo)
{
    int n = blockIdx.x;                  // gate-interleaved row: n = 4*j + g
    int j = n >> 2, g = n & 3;
    const float4* src = (const float4*)(W + ((size_t)g * HID + j) * HID);
    size_t dst = (size_t)n * HID;
#pragma unroll
    for (int r = 0; r < 2; ++r) {
        int q = threadIdx.x + 256 * r;
        float4 v = src[q];
        int k = q * 4;
        float xs[4] = {v.x, v.y, v.z, v.w};
#pragma unroll
        for (int c = 0; c < 4; ++c) {
            __nv_bfloat16 hi = __float2bfloat16(xs[c]);
            whi[dst + k + c] = hi;
            wlo[dst + k + c] = __float2bfloat16(xs[c] - __bfloat162float(hi));
        }
    }
}

__global__ void init_kernel(float* __restrict__ cbuf,
                            __nv_bfloat16* __restrict__ h0hi,
                            __nv_bfloat16* __restrict__ h0lo,
                            float* __restrict__ out,
                            const float* __restrict__ b_lin)
{
    int i = blockIdx.x * blockDim.x + threadIdx.x;
    if (i < BH) {
        cbuf[i] = 0.0f;
        h0hi[i] = __float2bfloat16(0.0f);
        h0lo[i] = __float2bfloat16(0.0f);
    }
    if (i < BATCH * TTOT) out[i] = b_lin[0];
}

// ---------------- fused LSTM step: bf16x3, K=128 super-chunks, frag-pipelined ----------------
__global__ void __launch_bounds__(NT, 2)
lstm_step(const __nv_bfloat16* __restrict__ Ahi, const __nv_bfloat16* __restrict__ Alo,
          __nv_bfloat16* __restrict__ Ahi_n, __nv_bfloat16* __restrict__ Alo_n,
          float* __restrict__ cbuf,
          const __nv_bfloat16* __restrict__ Whi, const __nv_bfloat16* __restrict__ Wlo,
          const float* __restrict__ W_ih, const float* __restrict__ b_ih,
          const float* __restrict__ b_hh, const float* __restrict__ W_lin,
          float* __restrict__ out,
          const float* __restrict__ xvec, int xstride, int t)
{
    extern __shared__ char smem_raw[];
    const int tid  = threadIdx.x;
    const int wid  = tid >> 5;
    const int lane = tid & 31;
    const int warp_m = wid & 1;          // 2 x 32 rows
    const int warp_n = wid >> 1;         // 4 x 32 cols
    const int m0 = blockIdx.x * BM;
    const int n0 = blockIdx.y * BN;      // gate-interleaved col base
    const int j0 = n0 >> 2;

    uint32_t sb    = smem_u32(smem_raw);
    uint32_t sbase = (sb + 1023) & ~1023u;
    char*    ctrl  = smem_raw + (sbase - sb);
    uint32_t tiles = sbase + CTRL_B;
    float* bias_s = (float*)(ctrl + 0);      // 128
    float* wih_s  = (float*)(ctrl + 512);    // 128
    float* rowsum = (float*)(ctrl + 1024);   // 64
    float* wlin_s = (float*)(ctrl + 1536);   // 32

    if (tid < 128) {
        int j = j0 + (tid >> 2);
        int g = tid & 3;
        bias_s[tid] = b_ih[g * HID + j] + b_hh[g * HID + j];
        wih_s[tid]  = W_ih[g * HID + j];
    }
    if (tid < 64) rowsum[tid] = 0.0f;
    if (tid < 32) wlin_s[tid] = W_lin[j0 + tid];
    __syncthreads();

    // epilogue row this thread owns; prefetch x input now (long latency, value final)
    const bool oddl = (lane & 1);
    const int rloc0 = warp_m * 32 + (lane >> 2) + (oddl ? 8 : 0);
    float xin[2];
#pragma unroll
    for (int mf = 0; mf < 2; ++mf)
        xin[mf] = xvec[(size_t)(m0 + rloc0 + mf * 16) * xstride];

    // ---- hoisted per-thread load addressing (byte offsets) ----
    uint32_t swA[2], aoff[2];            // A: 64 rows x 8 16B units = 512; 2 iters
#pragma unroll
    for (int r = 0; r < 2; ++r) {
        int q   = tid + NT * r;
        int row = q >> 3;
        int cb  = (q & 7) * 16;
        swA[r]  = (uint32_t)(row * 128 + (cb ^ ((row & 7) * 16)));
        aoff[r] = (uint32_t)(((m0 + row) * HID) * 2 + cb);
    }
    uint32_t swB[4], boff[4];            // B: 128 rows x 8 = 1024; 4 iters
#pragma unroll
    for (int r = 0; r < 4; ++r) {
        int q   = tid + NT * r;
        int row = q >> 3;
        int cb  = (q & 7) * 16;
        swB[r]  = (uint32_t)(row * 128 + (cb ^ ((row & 7) * 16)));
        boff[r] = (uint32_t)(((n0 + row) * HID) * 2 + cb);
    }

    float acc[2][4][4];
#pragma unroll
    for (int i = 0; i < 2; ++i)
#pragma unroll
        for (int jf = 0; jf < 4; ++jf)
#pragma unroll
            for (int kf = 0; kf < 4; ++kf) acc[i][jf][kf] = 0.0f;

    // ldmatrix addressing (SW128: xor (row&7)*16, row-invariant per lane)
    const int xm = (lane & 7) * 16;
    int arow[2], brow[2];
#pragma unroll
    for (int mf = 0; mf < 2; ++mf)
        arow[mf] = (warp_m * 32 + mf * 16 + (lane & 15)) * 128;
#pragma unroll
    for (int q = 0; q < 2; ++q)
        brow[q] = (warp_n * 32 + q * 16 + (lane & 7) + ((lane & 16) ? 8 : 0)) * 128;
    const int acoladd = (lane & 16) ? 16 : 0;
    const int bcoladd = (lane & 8) ? 16 : 0;

    // ---- load one super-chunk (K=128 = two 64-K subtiles) into a stage ----
    auto load_super = [&](uint32_t st, const char* Ab, const char* Bb, uint32_t koffB) {
#pragma unroll
        for (int r = 0; r < 2; ++r) {
            cpa16(st + SUB_A1 + swA[r], Ab + aoff[r] + koffB);
            cpa16(st + SUB_A2 + swA[r], Ab + aoff[r] + koffB + 128);
        }
#pragma unroll
        for (int r = 0; r < 4; ++r) {
            cpa16(st + SUB_B1 + swB[r], Bb + boff[r] + koffB);
            cpa16(st + SUB_B2 + swB[r], Bb + boff[r] + koffB + 128);
        }
    };

    // per-k-step frag loader: s in 0..7 (subtile = s>>2, kk = s&3)
    auto load_frags = [&](uint32_t st, int s, uint32_t (*a)[4], uint32_t (*b)[4]) {
        uint32_t sta = st + ((s < 4) ? SUB_A1 : SUB_A2);
        uint32_t stb = st + ((s < 4) ? SUB_B1 : SUB_B2);
        int colA = (s & 3) * 32 + acoladd;
        int colB = (s & 3) * 32 + bcoladd;
#pragma unroll
        for (int mf = 0; mf < 2; ++mf)
            ldsm4(a[mf], sta + arow[mf] + (uint32_t)(colA ^ xm));
#pragma unroll
        for (int q = 0; q < 2; ++q)
            ldsm4(b[q], stb + brow[q] + (uint32_t)(colB ^ xm));
    };

    auto do_mmas = [&](uint32_t (*a)[4], uint32_t (*b)[4]) {
#pragma unroll
        for (int mf = 0; mf < 2; ++mf) {
#pragma unroll
            for (int nf = 0; nf < 4; ++nf) {
                const uint32_t bp[2] = { b[nf >> 1][(nf & 1) * 2],
                                         b[nf >> 1][(nf & 1) * 2 + 1] };
                mma16816(acc[mf][nf], a[mf], bp);
            }
        }
    };

    const char* AhiB = (const char*)Ahi;
    const char* AloB = (const char*)Alo;
    const char* WhiB = (const char*)Whi;
    const char* WloB = (const char*)Wlo;

    // Prologue: super-chunk 0 (product 0: Ahi x Whi) into stage 0
    load_super(tiles, AhiB, WhiB, 0);
    cpa_commit();

    uint32_t afr[2][2][4], bfr[2][2][4];   // double-buffered fragments

    for (int c = 0; c < NSUP; ++c) {
        cpa_wait<0>();
        __syncthreads();

        int cn = c + 1;
        if (cn < NSUP) {
            int p = cn >> 4;                       // 0: AhiWhi, 1: AhiWlo, 2: AloWhi
            const char* Ab = (p == 2) ? AloB : AhiB;
            const char* Bb = (p == 1) ? WloB : WhiB;
            load_super(tiles + (uint32_t)(cn & 1) * SUPER_B, Ab, Bb,
                       (uint32_t)(cn & 15) * 256);
        }
        cpa_commit();

        uint32_t st = tiles + (uint32_t)(c & 1) * SUPER_B;

        // software-pipelined 8 k-steps: LDSM(s+1) issued before HMMA(s)
        load_frags(st, 0, afr[0], bfr[0]);
#pragma unroll
        for (int s = 0; s < 8; ++s) {
            const int cur = s & 1;
            if (s < 7) load_frags(st, s + 1, afr[cur ^ 1], bfr[cur ^ 1]);
            do_mmas(afr[cur], bfr[cur]);
        }
    }

    // ---- epilogue: gate exchange + LSTM cell + prediction ----
    const int slot = (lane >> 1) & 1;

    // batch-prefetch c_prev (8 values, MLP overlap)
    float cprev[2][4];
#pragma unroll
    for (int mf = 0; mf < 2; ++mf) {
        const int m = m0 + rloc0 + mf * 16;
#pragma unroll
        for (int nf = 0; nf < 4; ++nf) {
            const int jl = warp_n * 8 + nf * 2 + slot;
            cprev[mf][nf] = cbuf[(size_t)m * HID + (j0 + jl)];
        }
    }

#pragma unroll
    for (int mf = 0; mf < 2; ++mf) {
        const int rloc = rloc0 + mf * 16;
        const int m = m0 + rloc;
        float predp = 0.0f;
#pragma unroll
        for (int nf = 0; nf < 4; ++nf) {
            float c0 = acc[mf][nf][0], c1 = acc[mf][nf][1];
            float c2 = acc[mf][nf][2], c3 = acc[mf][nf][3];
            float t0 = __shfl_xor_sync(0xffffffffu, c0, 1);
            float t1 = __shfl_xor_sync(0xffffffffu, c1, 1);
            float t2 = __shfl_xor_sync(0xffffffffu, c2, 1);
            float t3 = __shfl_xor_sync(0xffffffffu, c3, 1);
            float gi, gf, gg, go;
            if (!oddl) { gi = c0; gf = c1; gg = t0; go = t1; }
            else       { gi = t2; gf = t3; gg = c2; go = c3; }

            const int jl = warp_n * 8 + nf * 2 + slot;
            const int nb = jl * 4;
            gi += bias_s[nb + 0] + xin[mf] * wih_s[nb + 0];
            gf += bias_s[nb + 1] + xin[mf] * wih_s[nb + 1];
            gg += bias_s[nb + 2] + xin[mf] * wih_s[nb + 2];
            go += bias_s[nb + 3] + xin[mf] * wih_s[nb + 3];

            const size_t off = (size_t)m * HID + (j0 + jl);
            float cn = sig_f(gf) * cprev[mf][nf] + sig_f(gi) * tanh_f(gg);
            cbuf[off] = cn;
            float hn = sig_f(go) * tanh_f(cn);

            __nv_bfloat16 hi = __float2bfloat16(hn);
            Ahi_n[off] = hi;
            Alo_n[off] = __float2bfloat16(hn - __bfloat162float(hi));
            predp += hn * wlin_s[jl];
        }
        atomicAdd(&rowsum[rloc], predp);
    }
    __syncthreads();
    if (tid < 64)
        atomicAdd(&out[(size_t)(m0 + tid) * TTOT + t], rowsum[tid]);
}

// ---------------- host launch ----------------
extern "C" void kernel_launch(void* const* d_in, const int* in_sizes, int n_in,
                              void* d_out, int out_size) {
    const float* x     = (const float*)d_in[0];
    const float* W_ih  = (const float*)d_in[1];
    const float* W_hh  = (const float*)d_in[2];
    const float* b_ih  = (const float*)d_in[3];
    const float* b_hh  = (const float*)d_in[4];
    const float* W_lin = (const float*)d_in[5];
    const float* b_lin = (const float*)d_in[6];
    float* out = (float*)d_out;

    float *cbuf;
    __nv_bfloat16 *hhi, *hlo, *whi, *wlo;
    cudaGetSymbolAddress((void**)&cbuf, g_c);
    cudaGetSymbolAddress((void**)&hhi,  g_hhi);
    cudaGetSymbolAddress((void**)&hlo,  g_hlo);
    cudaGetSymbolAddress((void**)&whi,  g_whi);
    cudaGetSymbolAddress((void**)&wlo,  g_wlo);

    cudaFuncSetAttribute(lstm_step, cudaFuncAttributeMaxDynamicSharedMemorySize, SMEM_DYN);

    wconv_kernel<<<HID4, 256>>>(W_hh, whi, wlo);
    init_kernel<<<(BH + 255) / 256, 256>>>(cbuf, hhi, hlo, out, b_lin);

    dim3 grid(BATCH / BM, HID4 / BN);

    for (int t = 0; t < TTOT; ++t) {
        const int cur = t & 1;
        const float* xvec;
        int xstride;
        if (t < TOBS) { xvec = x + t;         xstride = TOBS; }
        else          { xvec = out + (t - 1); xstride = TTOT; }

        lstm_step<<<grid, NT, SMEM_DYN>>>(
            hhi + (size_t)cur * BH, hlo + (size_t)cur * BH,
            hhi + (size_t)(1 - cur) * BH, hlo + (size_t)(1 - cur) * BH,
            cbuf, whi, wlo,
            W_ih, b_ih, b_hh, W_lin,
            out, xvec, xstride, t);
    }
}